// round 12
// baseline (speedup 1.0000x reference)
#include <cuda_runtime.h>
#include <cuda_bf16.h>
#include <cstdint>

#define NT 256

// Fragment-major bf16 weights: each uint4 = one lane's mma-A fragment (a0,a1,a2,a3)
// conv2: [9 tap][8 mblk][8 kblk][32 lane]  = 18432 uint4
// conv3: [9 tap][4 mblk][8 kblk][32 lane]  = 9216 uint4
// conv4: [9 tap][4 mblk][4 kblk][32 lane]  = 4608 uint4
__device__ uint4 g_w2f[18432];
__device__ uint4 g_w3f[9216];
__device__ uint4 g_w4f[4608];

__global__ void convert_weights(const float* __restrict__ w2,
                                const float* __restrict__ w3,
                                const float* __restrict__ w4) {
    int gid = blockIdx.x * blockDim.x + threadIdx.x;
    int stride = gridDim.x * blockDim.x;
    for (int u = gid; u < 18432; u += stride) {
        int lane = u & 31, k = (u >> 5) & 7, mb = (u >> 8) & 7, tap = u >> 11;
        int r = lane >> 2, c0 = (lane & 3) * 2;
        int co = mb * 16 + r, ci = k * 16 + c0;
        const float* Wt = w2 + tap * 16384;
        uint4 v;
        __nv_bfloat162 p;
        p = __floats2bfloat162_rn(Wt[ci * 128 + co],       Wt[(ci + 1) * 128 + co]);       v.x = *(uint32_t*)&p;
        p = __floats2bfloat162_rn(Wt[ci * 128 + co + 8],   Wt[(ci + 1) * 128 + co + 8]);   v.y = *(uint32_t*)&p;
        p = __floats2bfloat162_rn(Wt[(ci + 8) * 128 + co], Wt[(ci + 9) * 128 + co]);       v.z = *(uint32_t*)&p;
        p = __floats2bfloat162_rn(Wt[(ci + 8) * 128 + co + 8], Wt[(ci + 9) * 128 + co + 8]); v.w = *(uint32_t*)&p;
        g_w2f[u] = v;
    }
    for (int u = gid; u < 9216; u += stride) {
        int lane = u & 31, k = (u >> 5) & 7, mb = (u >> 8) & 3, tap = u >> 10;
        int r = lane >> 2, c0 = (lane & 3) * 2;
        int co = mb * 16 + r, ci = k * 16 + c0;
        const float* Wt = w3 + tap * 8192;
        uint4 v;
        __nv_bfloat162 p;
        p = __floats2bfloat162_rn(Wt[ci * 64 + co],       Wt[(ci + 1) * 64 + co]);       v.x = *(uint32_t*)&p;
        p = __floats2bfloat162_rn(Wt[ci * 64 + co + 8],   Wt[(ci + 1) * 64 + co + 8]);   v.y = *(uint32_t*)&p;
        p = __floats2bfloat162_rn(Wt[(ci + 8) * 64 + co], Wt[(ci + 9) * 64 + co]);       v.z = *(uint32_t*)&p;
        p = __floats2bfloat162_rn(Wt[(ci + 8) * 64 + co + 8], Wt[(ci + 9) * 64 + co + 8]); v.w = *(uint32_t*)&p;
        g_w3f[u] = v;
    }
    for (int u = gid; u < 4608; u += stride) {
        int lane = u & 31, k = (u >> 5) & 3, mb = (u >> 7) & 3, tap = u >> 9;
        int r = lane >> 2, c0 = (lane & 3) * 2;
        int co = mb * 16 + r, ci = k * 16 + c0;
        const float* Wt = w4 + tap * 4096;
        uint4 v;
        __nv_bfloat162 p;
        p = __floats2bfloat162_rn(Wt[ci * 64 + co],       Wt[(ci + 1) * 64 + co]);       v.x = *(uint32_t*)&p;
        p = __floats2bfloat162_rn(Wt[ci * 64 + co + 8],   Wt[(ci + 1) * 64 + co + 8]);   v.y = *(uint32_t*)&p;
        p = __floats2bfloat162_rn(Wt[(ci + 8) * 64 + co], Wt[(ci + 9) * 64 + co]);       v.z = *(uint32_t*)&p;
        p = __floats2bfloat162_rn(Wt[(ci + 8) * 64 + co + 8], Wt[(ci + 9) * 64 + co + 8]); v.w = *(uint32_t*)&p;
        g_w4f[u] = v;
    }
}

// ---------------- SMEM layout (byte offsets), 2 images per CTA, 3 CTAs/SM ----------------
#define S_ACT1   0          // 2 x [100 pos][136 ci] bf16 (stride 272B) = 54400
#define S_ACT4   0          // [64co][104n] stride 208 = 13312 (act1 dead by then)
#define S_ACT3   13312      // [50][72] bf16 stride 144 = 7200 (inside dead act1 p=0)
#define S_POOL2  54400      // [50][136] bf16 stride 272 = 13600
#define S_IMG    54400      // 200 f32 overlay (conv1 phase; pool2 not yet live)
#define S_FEAT   54400      // head phase overlays (pool2 dead)
#define S_H      54912
#define S_SV     55168
#define S_ZERO   68000      // 272 zero row
#define S_B2     68272
#define S_B3     68784
#define S_B4     69040
#define S_BD1    69296
#define S_BD2    69424
#define S_WD2    69440
#define SMEM_TOTAL 69952

__device__ __forceinline__ uint32_t smem_u32(const void* p) {
    uint32_t a;
    asm("{ .reg .u64 t; cvta.to.shared.u64 t, %1; cvt.u32.u64 %0, t; }" : "=r"(a) : "l"(p));
    return a;
}

__device__ __forceinline__ void mma16816(float* c, uint32_t a0, uint32_t a1, uint32_t a2,
                                         uint32_t a3, uint32_t b0, uint32_t b1) {
    asm volatile(
        "mma.sync.aligned.m16n8k16.row.col.f32.bf16.bf16.f32 "
        "{%0,%1,%2,%3},{%4,%5,%6,%7},{%8,%9},{%0,%1,%2,%3};\n"
        : "+f"(c[0]), "+f"(c[1]), "+f"(c[2]), "+f"(c[3])
        : "r"(a0), "r"(a1), "r"(a2), "r"(a3), "r"(b0), "r"(b1));
}

__device__ __forceinline__ void ldmx2(uint32_t& b0, uint32_t& b1, uint32_t addr) {
    asm volatile("ldmatrix.sync.aligned.m8n8.x2.shared.b16 {%0,%1},[%2];"
                 : "=r"(b0), "=r"(b1) : "r"(addr));
}

__global__ __launch_bounds__(NT, 3)
void img2svg_mma(const float* __restrict__ data,
                 const float* __restrict__ w1, const float* __restrict__ b1,
                 const float* __restrict__ b2v, const float* __restrict__ b3v,
                 const float* __restrict__ b4v,
                 const float* __restrict__ wd1, const float* __restrict__ bd1,
                 const float* __restrict__ wd2, const float* __restrict__ bd2,
                 float* __restrict__ out, int Btot) {
    extern __shared__ char sm[];
    const int tid = threadIdx.x;
    const int wid = tid >> 5, lane = tid & 31;
    const int dlt = lane >> 2, q = lane & 3;
    const uint32_t sbase = smem_u32(sm);
    const int rB = lane & 7;                             // B row within frag
    const int hB = ((lane >> 3) & 1) * 16;               // k-half select for x2
    const uint32_t zAddr = sbase + (uint32_t)(S_ZERO + hB);

    float* s_b2  = (float*)(sm + S_B2);
    float* s_b3  = (float*)(sm + S_B3);
    float* s_b4  = (float*)(sm + S_B4);
    float* s_bd1 = (float*)(sm + S_BD1);
    float* s_bd2 = (float*)(sm + S_BD2);
    float* s_wd2 = (float*)(sm + S_WD2);
    float* s_feat = (float*)(sm + S_FEAT);
    float* s_h   = (float*)(sm + S_H);
    float* s_sv  = (float*)(sm + S_SV);
    float* s_img = (float*)(sm + S_IMG);

    // ---- init loads ----
    if (tid < 128) s_b2[tid] = b2v[tid];
    if (tid < 64)  s_b3[tid] = b3v[tid];
    if (tid < 64)  s_b4[tid] = b4v[tid];
    if (tid < 32)  s_bd1[tid] = bd1[tid];
    if (tid < 4)   s_bd2[tid] = bd2[tid];
    if (tid < 128) s_wd2[tid] = wd2[tid];
    if (tid < 68)  *(uint32_t*)(sm + S_ZERO + tid * 4) = 0u;
    {
        long long base = (long long)blockIdx.x * 200;
        for (int e = tid; e < 200; e += NT) {
            long long gi = base + e;
            s_img[e] = (gi < (long long)Btot * 100) ? data[gi] : 0.f;
        }
    }
    __syncthreads();

    // ---- conv1 (scalar): 1 -> 128, relu -> act1[img][pos][ci] bf16 ----
    {
        const int img = tid >> 7, co = tid & 127;
        const float* ip = s_img + img * 100;
        float wv[9];
        #pragma unroll
        for (int t = 0; t < 9; t++) wv[t] = w1[t * 128 + co];
        const float bias = b1[co];
        for (int pos = 0; pos < 100; pos++) {
            int r = pos / 10, c = pos - r * 10;
            float acc = bias;
            #pragma unroll
            for (int dy = -1; dy <= 1; dy++) {
                int rr = r + dy;
                if ((unsigned)rr < 10u) {
                    #pragma unroll
                    for (int dx = -1; dx <= 1; dx++) {
                        int cc = c + dx;
                        if ((unsigned)cc < 10u)
                            acc += wv[(dy + 1) * 3 + dx + 1] * ip[rr * 10 + cc];
                    }
                }
            }
            *(__nv_bfloat16*)(sm + S_ACT1 + (img * 100 + pos) * 272 + co * 2) =
                __float2bfloat16(fmaxf(acc, 0.f));
        }
    }
    __syncthreads();

    // ---- conv2 + fused maxpool ----
    // Frags are pooling-aligned blocks: frag f (0..14): a=f/3 (row pair), b=f%3 (col quad).
    // Lane rB -> pos row 2a+(rB&1), col 4b+(rB>>1). Warp ng owns f = ng + 2u.
    // Two n-passes (u in 0..3 / 4..7) to keep C at 32 regs.
    for (int p = 0; p < 2; p++) {
        const int mg = wid >> 1, ng = wid & 1;
        const uint32_t bBase = sbase + (uint32_t)(S_ACT1 + p * 27200 + hB);
        const uint4* W = g_w2f + (mg * 2) * 256 + lane;    // + t*2048 + mt*256 + k*32

        for (int nh = 0; nh < 2; nh++) {
            const int nf = (nh == 0) ? 4 : (ng == 0 ? 4 : 3);
            float C0[4][4], C1[4][4];
            #pragma unroll
            for (int j = 0; j < 4; j++)
                #pragma unroll
                for (int k = 0; k < 4; k++) { C0[j][k] = 0.f; C1[j][k] = 0.f; }

            int rowb[4], colb[4];
            #pragma unroll
            for (int u2 = 0; u2 < 4; u2++) {
                int f = ng + 2 * (nh * 4 + u2);
                if (f < 15) {
                    int a = f / 3, b = f - 3 * (f / 3);
                    rowb[u2] = 2 * a + (rB & 1);
                    colb[u2] = 4 * b + (rB >> 1);
                } else { rowb[u2] = -100; colb[u2] = 0; }
            }

            for (int t = 0; t < 9; t++) {
                const int dy = t / 3 - 1, dx = t % 3 - 1;
                uint32_t bA[4];
                #pragma unroll
                for (int u2 = 0; u2 < 4; u2++) {
                    int rr = rowb[u2] + dy, cc = colb[u2] + dx;
                    bool ok = ((unsigned)rr < 10u) && ((unsigned)cc < 10u);
                    bA[u2] = ok ? bBase + (uint32_t)((rr * 10 + cc) * 272) : zAddr;
                }
                const uint4* Wt = W + t * 2048;
                uint4 a0c = __ldg(Wt), a1c = __ldg(Wt + 256);
                #pragma unroll
                for (int k = 0; k < 8; k++) {
                    uint4 a0n, a1n;
                    if (k < 7) { a0n = __ldg(Wt + (k + 1) * 32); a1n = __ldg(Wt + 256 + (k + 1) * 32); }
                    #pragma unroll
                    for (int j = 0; j < 4; j++) {
                        if (j < nf) {
                            uint32_t b0, b1;
                            ldmx2(b0, b1, bA[j] + 32 * k);
                            mma16816(C0[j], a0c.x, a0c.y, a0c.z, a0c.w, b0, b1);
                            mma16816(C1[j], a1c.x, a1c.y, a1c.z, a1c.w, b0, b1);
                        }
                    }
                    a0c = a0n; a1c = a1n;
                }
            }

            // fused epilogue: bias + 2x2 maxpool in registers -> pooled2
            // c[0],c[1] = image rows 2a,2a+1 at col 4b+q (co=dlt-row); c[2],c[3] same for co+8.
            #pragma unroll
            for (int u2 = 0; u2 < 4; u2++) {
                if (u2 < nf) {
                    int f = ng + 2 * (nh * 4 + u2);
                    int a = f / 3, b = f - 3 * (f / 3);
                    #pragma unroll
                    for (int mt = 0; mt < 2; mt++) {
                        float* c = mt ? C1[u2] : C0[u2];
                        float m01 = fmaxf(c[0], c[1]);
                        float m23 = fmaxf(c[2], c[3]);
                        float o01 = fmaxf(m01, __shfl_xor_sync(0xffffffffu, m01, 1));
                        float o23 = fmaxf(m23, __shfl_xor_sync(0xffffffffu, m23, 1));
                        int pc = 2 * b + (q >> 1);
                        if (((q & 1) == 0) && pc < 5) {
                            int co = mg * 32 + mt * 16 + dlt;
                            int pp = p * 25 + a * 5 + pc;
                            *(__nv_bfloat16*)(sm + S_POOL2 + pp * 272 + co * 2) =
                                __float2bfloat16(fmaxf(o01 + s_b2[co], 0.f));
                            *(__nv_bfloat16*)(sm + S_POOL2 + pp * 272 + (co + 8) * 2) =
                                __float2bfloat16(fmaxf(o23 + s_b2[co + 8], 0.f));
                        }
                    }
                }
            }
        }
    }
    __syncthreads();   // pooled2 complete for both images

    // ---- conv3: M=64, N=50 (2img x 25pos), K=128/tap; 8 warps m32n16, barrier-free ----
    {
        const int mg = wid & 1, ng = wid >> 1;           // ng 0..3
        const int njeff = (ng == 3) ? 1 : 2;
        float D0[2][4], D1[2][4];
        #pragma unroll
        for (int j = 0; j < 2; j++)
            #pragma unroll
            for (int k = 0; k < 4; k++) { D0[j][k] = 0.f; D1[j][k] = 0.f; }

        int rj[2], cj[2];
        uint32_t aj[2];
        #pragma unroll
        for (int j = 0; j < 2; j++) {
            int n = ng * 16 + j * 8 + rB;
            int img = n / 25, pos = n - img * 25;
            rj[j] = (n < 50) ? (pos / 5) : -100;
            cj[j] = pos - (pos / 5) * 5;
            aj[j] = sbase + (uint32_t)(S_POOL2 + img * 25 * 272 + hB);
        }
        const uint4* W = g_w3f + (mg * 2) * 256 + lane;   // + t*1024 + mt*256 + k*32

        for (int t = 0; t < 9; t++) {
            const int dy = t / 3 - 1, dx = t % 3 - 1;
            uint32_t bA[2];
            #pragma unroll
            for (int j = 0; j < 2; j++) {
                int rr = rj[j] + dy, cc = cj[j] + dx;
                bool ok = ((unsigned)rr < 5u) && ((unsigned)cc < 5u);
                bA[j] = ok ? aj[j] + (uint32_t)((rr * 5 + cc) * 272) : zAddr;
            }
            const uint4* Wt = W + t * 1024;
            uint4 a0c = __ldg(Wt), a1c = __ldg(Wt + 256);
            #pragma unroll
            for (int k = 0; k < 8; k++) {
                uint4 a0n, a1n;
                if (k < 7) { a0n = __ldg(Wt + (k + 1) * 32); a1n = __ldg(Wt + 256 + (k + 1) * 32); }
                #pragma unroll
                for (int j = 0; j < 2; j++) {
                    if (j < njeff) {
                        uint32_t b0, b1;
                        ldmx2(b0, b1, bA[j] + 32 * k);
                        mma16816(D0[j], a0c.x, a0c.y, a0c.z, a0c.w, b0, b1);
                        mma16816(D1[j], a1c.x, a1c.y, a1c.z, a1c.w, b0, b1);
                    }
                }
                a0c = a0n; a1c = a1n;
            }
        }
        __syncthreads();   // pooled2 reads done before act3 write (act3 in dead act1)
        #pragma unroll
        for (int mt = 0; mt < 2; mt++) {
            #pragma unroll
            for (int j = 0; j < 2; j++) {
                float* c = mt ? D1[j] : D0[j];
                int co = mg * 32 + mt * 16 + dlt;
                int n0 = ng * 16 + j * 8 + 2 * q;
                if (n0 < 50) {
                    float bAv = s_b3[co], bBv = s_b3[co + 8];
                    *(__nv_bfloat16*)(sm + S_ACT3 + n0 * 144 + co * 2) =
                        __float2bfloat16(fmaxf(c[0] + bAv, 0.f));
                    *(__nv_bfloat16*)(sm + S_ACT3 + (n0 + 1) * 144 + co * 2) =
                        __float2bfloat16(fmaxf(c[1] + bAv, 0.f));
                    *(__nv_bfloat16*)(sm + S_ACT3 + n0 * 144 + (co + 8) * 2) =
                        __float2bfloat16(fmaxf(c[2] + bBv, 0.f));
                    *(__nv_bfloat16*)(sm + S_ACT3 + (n0 + 1) * 144 + (co + 8) * 2) =
                        __float2bfloat16(fmaxf(c[3] + bBv, 0.f));
                }
            }
        }
        __syncthreads();
    }

    // ---- conv4: M=64, N=50, K=64/tap; 8 warps m32n16, barrier-free ----
    {
        const int mg = wid & 1, ng = wid >> 1;
        const int njeff = (ng == 3) ? 1 : 2;
        float D0[2][4], D1[2][4];
        #pragma unroll
        for (int j = 0; j < 2; j++)
            #pragma unroll
            for (int k = 0; k < 4; k++) { D0[j][k] = 0.f; D1[j][k] = 0.f; }

        int rj[2], cj[2];
        uint32_t aj[2];
        #pragma unroll
        for (int j = 0; j < 2; j++) {
            int n = ng * 16 + j * 8 + rB;
            int img = n / 25, pos = n - img * 25;
            rj[j] = (n < 50) ? (pos / 5) : -100;
            cj[j] = pos - (pos / 5) * 5;
            aj[j] = sbase + (uint32_t)(S_ACT3 + img * 25 * 144 + hB);
        }
        const uint4* W = g_w4f + (mg * 2) * 128 + lane;   // + t*512 + mt*128 + k*32

        for (int t = 0; t < 9; t++) {
            const int dy = t / 3 - 1, dx = t % 3 - 1;
            uint32_t bA[2];
            #pragma unroll
            for (int j = 0; j < 2; j++) {
                int rr = rj[j] + dy, cc = cj[j] + dx;
                bool ok = ((unsigned)rr < 5u) && ((unsigned)cc < 5u);
                bA[j] = ok ? aj[j] + (uint32_t)((rr * 5 + cc) * 144) : zAddr;
            }
            const uint4* Wt = W + t * 512;
            uint4 a0c = __ldg(Wt), a1c = __ldg(Wt + 128);
            #pragma unroll
            for (int k = 0; k < 4; k++) {
                uint4 a0n, a1n;
                if (k < 3) { a0n = __ldg(Wt + (k + 1) * 32); a1n = __ldg(Wt + 128 + (k + 1) * 32); }
                #pragma unroll
                for (int j = 0; j < 2; j++) {
                    if (j < njeff) {
                        uint32_t b0, b1;
                        ldmx2(b0, b1, bA[j] + 32 * k);
                        mma16816(D0[j], a0c.x, a0c.y, a0c.z, a0c.w, b0, b1);
                        mma16816(D1[j], a1c.x, a1c.y, a1c.z, a1c.w, b0, b1);
                    }
                }
                a0c = a0n; a1c = a1n;
            }
        }
        __syncthreads();   // act3 reads done before act4 write region reuse
        #pragma unroll
        for (int mt = 0; mt < 2; mt++) {
            #pragma unroll
            for (int j = 0; j < 2; j++) {
                float* c = mt ? D1[j] : D0[j];
                int co = mg * 32 + mt * 16 + dlt;
                int n0 = ng * 16 + j * 8 + 2 * q;
                if (n0 < 50) {
                    float bAv = s_b4[co], bBv = s_b4[co + 8];
                    __nv_bfloat162 v01 = __floats2bfloat162_rn(fmaxf(c[0] + bAv, 0.f),
                                                               fmaxf(c[1] + bAv, 0.f));
                    __nv_bfloat162 v23 = __floats2bfloat162_rn(fmaxf(c[2] + bBv, 0.f),
                                                               fmaxf(c[3] + bBv, 0.f));
                    *(uint32_t*)(sm + S_ACT4 + co * 208 + n0 * 2) = *(uint32_t*)&v01;
                    *(uint32_t*)(sm + S_ACT4 + (co + 8) * 208 + n0 * 2) = *(uint32_t*)&v23;
                }
            }
        }
        __syncthreads();
    }

    // ---- head: pool 2x2 -> mean -> dense -> sigmoid ----
    if (tid < 128) {
        int img = tid >> 6, c = tid & 63;
        const char* b = sm + S_ACT4 + c * 208 + img * 50;
        #define GA(p) __bfloat162float(*(const __nv_bfloat16*)(b + (p) * 2))
        float m00 = fmaxf(fmaxf(GA(0), GA(1)), fmaxf(GA(5), GA(6)));
        float m01 = fmaxf(fmaxf(GA(2), GA(3)), fmaxf(GA(7), GA(8)));
        float m10 = fmaxf(fmaxf(GA(10), GA(11)), fmaxf(GA(15), GA(16)));
        float m11 = fmaxf(fmaxf(GA(12), GA(13)), fmaxf(GA(17), GA(18)));
        #undef GA
        s_feat[img * 64 + c] = 0.25f * (m00 + m01 + m10 + m11);
    }
    __syncthreads();
    if (tid < 64) {
        int img = tid >> 5, jn = tid & 31;
        float acc = s_bd1[jn];
        #pragma unroll 8
        for (int c = 0; c < 64; c++) acc += s_feat[img * 64 + c] * __ldg(wd1 + c * 32 + jn);
        s_h[img * 32 + jn] = fmaxf(acc, 0.f);
    }
    __syncthreads();
    if (tid < 8) {
        int img = tid >> 2, k = tid & 3;
        float acc = s_bd2[k];
        #pragma unroll 8
        for (int j = 0; j < 32; j++) acc += s_h[img * 32 + j] * s_wd2[j * 4 + k];
        s_sv[img * 4 + k] = 1.f / (1.f + expf(-acc));
    }
    __syncthreads();
    if (tid < 2) {
        int gimg = blockIdx.x * 2 + tid;
        if (gimg < Btot) {
            const float* sv = s_sv + tid * 4;
            const float p1x = sv[0], p1y = sv[1], p2x = sv[2], p2y = sv[3];
            float px[5], py[5], pos[5];
            #pragma unroll
            for (int i = 0; i < 5; i++) {
                float t = 0.25f * (float)i;
                float x = rintf(((1.f - t) * p1x + t * p2x) * 10.f);
                float y = rintf(((1.f - t) * p1y + t * p2y) * 10.f);
                px[i] = x; py[i] = y;
                pos[i] = x * 10.f + y;
            }
            int ord[5] = {0, 1, 2, 3, 4};
            for (int i = 1; i < 5; i++) {
                int key = ord[i]; float kp = pos[key]; int j = i - 1;
                while (j >= 0 && pos[ord[j]] > kp) { ord[j + 1] = ord[j]; j--; }
                ord[j + 1] = key;
            }
            float ox[5], oy[5];
            #pragma unroll
            for (int i = 0; i < 5; i++) { ox[i] = px[ord[i]]; oy[i] = py[ord[i]]; }
            float o[10];
            #pragma unroll
            for (int i = 0; i < 10; i++) o[i] = -1.f;
            o[0] = ox[0]; o[1] = oy[0];
            int dst = 1;
            for (int i = 1; i < 5; i++) {
                float d = fabsf(ox[i] - ox[i - 1]) + fabsf(oy[i] - oy[i - 1]);
                if (d != 0.f) { o[2 * dst] = ox[i]; o[2 * dst + 1] = oy[i]; dst++; }
            }
            float* op = out + (long long)gimg * 10;
            #pragma unroll
            for (int i = 0; i < 10; i++) op[i] = o[i];
        }
    }
}

extern "C" void kernel_launch(void* const* d_in, const int* in_sizes, int n_in,
                              void* d_out, int out_size) {
    const float* data = (const float*)d_in[0];
    const float* w1   = (const float*)d_in[1];
    const float* b1   = (const float*)d_in[2];
    const float* w2   = (const float*)d_in[3];
    const float* b2   = (const float*)d_in[4];
    const float* w3   = (const float*)d_in[5];
    const float* b3   = (const float*)d_in[6];
    const float* w4   = (const float*)d_in[7];
    const float* b4   = (const float*)d_in[8];
    const float* wd1  = (const float*)d_in[9];
    const float* bd1  = (const float*)d_in[10];
    const float* wd2  = (const float*)d_in[11];
    const float* bd2  = (const float*)d_in[12];
    float* out = (float*)d_out;
    const int B = in_sizes[0] / 100;

    cudaFuncSetAttribute(img2svg_mma, cudaFuncAttributeMaxDynamicSharedMemorySize, SMEM_TOTAL);

    convert_weights<<<96, 256>>>(w2, w3, w4);
    img2svg_mma<<<(B + 1) / 2, NT, SMEM_TOTAL>>>(data, w1, b1, b2, b3, b4,
                                                 wd1, bd1, wd2, bd2, out, B);
}

// round 13
// speedup vs baseline: 1.1374x; 1.1374x over previous
#include <cuda_runtime.h>
#include <cuda_bf16.h>
#include <cstdint>

#define NT 256

// Fragment-major bf16 weights: each uint4 = one lane's mma-A fragment (a0,a1,a2,a3)
// conv2: [9 tap][8 mblk][8 kblk][32 lane]  = 18432 uint4
// conv3: [9 tap][4 mblk][8 kblk][32 lane]  = 9216 uint4
// conv4: [9 tap][4 mblk][4 kblk][32 lane]  = 4608 uint4
__device__ uint4 g_w2f[18432];
__device__ uint4 g_w3f[9216];
__device__ uint4 g_w4f[4608];

__global__ void convert_weights(const float* __restrict__ w2,
                                const float* __restrict__ w3,
                                const float* __restrict__ w4) {
    int gid = blockIdx.x * blockDim.x + threadIdx.x;
    int stride = gridDim.x * blockDim.x;
    for (int u = gid; u < 18432; u += stride) {
        int lane = u & 31, k = (u >> 5) & 7, mb = (u >> 8) & 7, tap = u >> 11;
        int r = lane >> 2, c0 = (lane & 3) * 2;
        int co = mb * 16 + r, ci = k * 16 + c0;
        const float* Wt = w2 + tap * 16384;
        uint4 v;
        __nv_bfloat162 p;
        p = __floats2bfloat162_rn(Wt[ci * 128 + co],       Wt[(ci + 1) * 128 + co]);       v.x = *(uint32_t*)&p;
        p = __floats2bfloat162_rn(Wt[ci * 128 + co + 8],   Wt[(ci + 1) * 128 + co + 8]);   v.y = *(uint32_t*)&p;
        p = __floats2bfloat162_rn(Wt[(ci + 8) * 128 + co], Wt[(ci + 9) * 128 + co]);       v.z = *(uint32_t*)&p;
        p = __floats2bfloat162_rn(Wt[(ci + 8) * 128 + co + 8], Wt[(ci + 9) * 128 + co + 8]); v.w = *(uint32_t*)&p;
        g_w2f[u] = v;
    }
    for (int u = gid; u < 9216; u += stride) {
        int lane = u & 31, k = (u >> 5) & 7, mb = (u >> 8) & 3, tap = u >> 10;
        int r = lane >> 2, c0 = (lane & 3) * 2;
        int co = mb * 16 + r, ci = k * 16 + c0;
        const float* Wt = w3 + tap * 8192;
        uint4 v;
        __nv_bfloat162 p;
        p = __floats2bfloat162_rn(Wt[ci * 64 + co],       Wt[(ci + 1) * 64 + co]);       v.x = *(uint32_t*)&p;
        p = __floats2bfloat162_rn(Wt[ci * 64 + co + 8],   Wt[(ci + 1) * 64 + co + 8]);   v.y = *(uint32_t*)&p;
        p = __floats2bfloat162_rn(Wt[(ci + 8) * 64 + co], Wt[(ci + 9) * 64 + co]);       v.z = *(uint32_t*)&p;
        p = __floats2bfloat162_rn(Wt[(ci + 8) * 64 + co + 8], Wt[(ci + 9) * 64 + co + 8]); v.w = *(uint32_t*)&p;
        g_w3f[u] = v;
    }
    for (int u = gid; u < 4608; u += stride) {
        int lane = u & 31, k = (u >> 5) & 3, mb = (u >> 7) & 3, tap = u >> 9;
        int r = lane >> 2, c0 = (lane & 3) * 2;
        int co = mb * 16 + r, ci = k * 16 + c0;
        const float* Wt = w4 + tap * 4096;
        uint4 v;
        __nv_bfloat162 p;
        p = __floats2bfloat162_rn(Wt[ci * 64 + co],       Wt[(ci + 1) * 64 + co]);       v.x = *(uint32_t*)&p;
        p = __floats2bfloat162_rn(Wt[ci * 64 + co + 8],   Wt[(ci + 1) * 64 + co + 8]);   v.y = *(uint32_t*)&p;
        p = __floats2bfloat162_rn(Wt[(ci + 8) * 64 + co], Wt[(ci + 9) * 64 + co]);       v.z = *(uint32_t*)&p;
        p = __floats2bfloat162_rn(Wt[(ci + 8) * 64 + co + 8], Wt[(ci + 9) * 64 + co + 8]); v.w = *(uint32_t*)&p;
        g_w4f[u] = v;
    }
}

// ---------------- SMEM layout (byte offsets), 2 images per CTA ----------------
#define S_ACT1   0          // 2 x [100 pos][136 ci] bf16 (stride 272B) = 54400
#define S_POOL2  54400      // [50][136] bf16 stride 272 = 13600
#define S_ACT3   68000      // [50][72] bf16 stride 144 = 7200
#define S_ZERO   75200      // 272 zero row
#define S_B2     75472
#define S_B3     75984
#define S_B4     76240
#define S_BD1    76496
#define S_BD2    76624
#define S_WD2    76640
#define S_FEAT   77152
#define S_H      77664
#define S_SV     77920
#define S_IMG    77952
#define SMEM_TOTAL 78752
#define S_ACT4   0          // act4 scratch [64co][104n] stride 208 (act1 dead)

__device__ __forceinline__ uint32_t smem_u32(const void* p) {
    uint32_t a;
    asm("{ .reg .u64 t; cvta.to.shared.u64 t, %1; cvt.u32.u64 %0, t; }" : "=r"(a) : "l"(p));
    return a;
}

__device__ __forceinline__ void mma16816(float* c, uint32_t a0, uint32_t a1, uint32_t a2,
                                         uint32_t a3, uint32_t b0, uint32_t b1) {
    asm volatile(
        "mma.sync.aligned.m16n8k16.row.col.f32.bf16.bf16.f32 "
        "{%0,%1,%2,%3},{%4,%5,%6,%7},{%8,%9},{%0,%1,%2,%3};\n"
        : "+f"(c[0]), "+f"(c[1]), "+f"(c[2]), "+f"(c[3])
        : "r"(a0), "r"(a1), "r"(a2), "r"(a3), "r"(b0), "r"(b1));
}

__device__ __forceinline__ void ldmx4(uint32_t& b0, uint32_t& b1, uint32_t& b2, uint32_t& b3,
                                      uint32_t addr) {
    asm volatile("ldmatrix.sync.aligned.m8n8.x4.shared.b16 {%0,%1,%2,%3},[%4];"
                 : "=r"(b0), "=r"(b1), "=r"(b2), "=r"(b3) : "r"(addr));
}

__global__ __launch_bounds__(NT, 2)
void img2svg_mma(const float* __restrict__ data,
                 const float* __restrict__ w1, const float* __restrict__ b1,
                 const float* __restrict__ b2v, const float* __restrict__ b3v,
                 const float* __restrict__ b4v,
                 const float* __restrict__ wd1, const float* __restrict__ bd1,
                 const float* __restrict__ wd2, const float* __restrict__ bd2,
                 float* __restrict__ out, int Btot) {
    extern __shared__ char sm[];
    const int tid = threadIdx.x;
    const int wid = tid >> 5, lane = tid & 31;
    const int dlt = lane >> 2, q = lane & 3;
    const uint32_t sbase = smem_u32(sm);
    const int rB = lane & 7;                             // B row (n) within frag
    const int hB = ((lane >> 3) & 1) * 16;               // k-half byte offset
    const int hiSel = lane >> 4;                          // 0: frag 2u, 1: frag 2u+1
    const uint32_t zAddr = sbase + (uint32_t)(S_ZERO + hB);

    float* s_b2  = (float*)(sm + S_B2);
    float* s_b3  = (float*)(sm + S_B3);
    float* s_b4  = (float*)(sm + S_B4);
    float* s_bd1 = (float*)(sm + S_BD1);
    float* s_bd2 = (float*)(sm + S_BD2);
    float* s_wd2 = (float*)(sm + S_WD2);
    float* s_feat = (float*)(sm + S_FEAT);
    float* s_h   = (float*)(sm + S_H);
    float* s_sv  = (float*)(sm + S_SV);
    float* s_img = (float*)(sm + S_IMG);

    // ---- init loads ----
    if (tid < 128) s_b2[tid] = b2v[tid];
    if (tid < 64)  s_b3[tid] = b3v[tid];
    if (tid < 64)  s_b4[tid] = b4v[tid];
    if (tid < 32)  s_bd1[tid] = bd1[tid];
    if (tid < 4)   s_bd2[tid] = bd2[tid];
    if (tid < 128) s_wd2[tid] = wd2[tid];
    if (tid < 68)  *(uint32_t*)(sm + S_ZERO + tid * 4) = 0u;
    {
        long long base = (long long)blockIdx.x * 200;
        for (int e = tid; e < 200; e += NT) {
            long long gi = base + e;
            s_img[e] = (gi < (long long)Btot * 100) ? data[gi] : 0.f;
        }
    }
    __syncthreads();

    // ---- conv1 (scalar): 1 -> 128, relu -> act1[img][pos][ci] bf16 ----
    {
        const int img = tid >> 7, co = tid & 127;
        const float* ip = s_img + img * 100;
        float wv[9];
        #pragma unroll
        for (int t = 0; t < 9; t++) wv[t] = w1[t * 128 + co];
        const float bias = b1[co];
        for (int pos = 0; pos < 100; pos++) {
            int r = pos / 10, c = pos - r * 10;
            float acc = bias;
            #pragma unroll
            for (int dy = -1; dy <= 1; dy++) {
                int rr = r + dy;
                if ((unsigned)rr < 10u) {
                    #pragma unroll
                    for (int dx = -1; dx <= 1; dx++) {
                        int cc = c + dx;
                        if ((unsigned)cc < 10u)
                            acc += wv[(dy + 1) * 3 + dx + 1] * ip[rr * 10 + cc];
                    }
                }
            }
            *(__nv_bfloat16*)(sm + S_ACT1 + (img * 100 + pos) * 272 + co * 2) =
                __float2bfloat16(fmaxf(acc, 0.f));
        }
    }
    __syncthreads();

    // ---- conv2: per pass 1 image x 8 warps, warp m32 x n56, K=128/tap, barrier-free ----
    for (int p = 0; p < 2; p++) {
        const int mg = wid >> 1, ng = wid & 1;
        const int njeff = ng ? 6 : 7;
        const int npair = ng ? 3 : 4;
        float C0[7][4], C1[7][4];
        #pragma unroll
        for (int j = 0; j < 7; j++)
            #pragma unroll
            for (int k = 0; k < 4; k++) { C0[j][k] = 0.f; C1[j][k] = 0.f; }

        int rj[7], cj[7];
        #pragma unroll
        for (int j = 0; j < 7; j++) {
            int n = ng * 56 + j * 8 + rB;
            rj[j] = (n < 100) ? (n / 10) : -100;
            cj[j] = n - (n / 10) * 10;
        }
        const uint32_t bBase = sbase + (uint32_t)(S_ACT1 + p * 27200 + hB);
        const uint4* W = g_w2f + (mg * 2) * 256 + lane;    // + t*2048 + mt*256 + k*32

        for (int t = 0; t < 9; t++) {
            const int dy = t / 3 - 1, dx = t % 3 - 1;
            uint32_t bA[7];
            #pragma unroll
            for (int j = 0; j < 7; j++) {
                int rr = rj[j] + dy, cc = cj[j] + dx;
                bool ok = ((unsigned)rr < 10u) && ((unsigned)cc < 10u);
                bA[j] = ok ? bBase + (uint32_t)((rr * 10 + cc) * 272) : zAddr;
            }
            // per-lane dual-frag select: lanes<16 -> frag 2u, lanes>=16 -> frag 2u+1
            uint32_t bSel[4];
            bSel[0] = hiSel ? bA[1] : bA[0];
            bSel[1] = hiSel ? bA[3] : bA[2];
            bSel[2] = hiSel ? bA[5] : bA[4];
            bSel[3] = hiSel ? zAddr : bA[6];
            const uint4* Wt = W + t * 2048;
            uint4 a0c = __ldg(Wt), a1c = __ldg(Wt + 256);
            #pragma unroll
            for (int k = 0; k < 8; k++) {
                uint4 a0n, a1n;
                if (k < 7) { a0n = __ldg(Wt + (k + 1) * 32); a1n = __ldg(Wt + 256 + (k + 1) * 32); }
                #pragma unroll
                for (int u = 0; u < 4; u++) {
                    if (u < npair) {
                        uint32_t b0, b1, b2, b3;
                        ldmx4(b0, b1, b2, b3, bSel[u] + 32 * k);
                        mma16816(C0[2 * u], a0c.x, a0c.y, a0c.z, a0c.w, b0, b1);
                        mma16816(C1[2 * u], a1c.x, a1c.y, a1c.z, a1c.w, b0, b1);
                        if (2 * u + 1 < njeff) {
                            mma16816(C0[2 * u + 1], a0c.x, a0c.y, a0c.z, a0c.w, b2, b3);
                            mma16816(C1[2 * u + 1], a1c.x, a1c.y, a1c.z, a1c.w, b2, b3);
                        }
                    }
                }
                a0c = a0n; a1c = a1n;
            }
        }
        __syncthreads();   // all warps done reading act1[p]

        // epilogue: bias+relu -> scratch [co][104 n] (overlays act1 slot p)
        const uint32_t scr = S_ACT1 + (uint32_t)p * 27200;
        #pragma unroll
        for (int mt = 0; mt < 2; mt++) {
            #pragma unroll
            for (int j = 0; j < 7; j++) {
                float* c = mt ? C1[j] : C0[j];
                int co = mg * 32 + mt * 16 + dlt;
                int n0 = ng * 56 + j * 8 + 2 * q;
                if (n0 < 100) {
                    float bAv = s_b2[co], bBv = s_b2[co + 8];
                    __nv_bfloat162 v01 = __floats2bfloat162_rn(fmaxf(c[0] + bAv, 0.f),
                                                               fmaxf(c[1] + bAv, 0.f));
                    __nv_bfloat162 v23 = __floats2bfloat162_rn(fmaxf(c[2] + bBv, 0.f),
                                                               fmaxf(c[3] + bBv, 0.f));
                    *(uint32_t*)(sm + scr + co * 208 + n0 * 2) = *(uint32_t*)&v01;
                    *(uint32_t*)(sm + scr + (co + 8) * 208 + n0 * 2) = *(uint32_t*)&v23;
                }
            }
        }
        __syncthreads();
        // 2x2 maxpool -> pooled2[p*25+pp][ci]
        for (int e = tid; e < 3200; e += NT) {
            int co = e & 127, pp = e >> 7;
            int pr = pp / 5, pc = pp - pr * 5;
            int ntop = pr * 20 + pc * 2;
            uint32_t topw = *(uint32_t*)(sm + scr + co * 208 + ntop * 2);
            uint32_t botw = *(uint32_t*)(sm + scr + co * 208 + (ntop + 10) * 2);
            float2 tf = __bfloat1622float2(*(__nv_bfloat162*)&topw);
            float2 bf = __bfloat1622float2(*(__nv_bfloat162*)&botw);
            float m = fmaxf(fmaxf(tf.x, tf.y), fmaxf(bf.x, bf.y));
            *(__nv_bfloat16*)(sm + S_POOL2 + (p * 25 + pp) * 272 + co * 2) =
                __float2bfloat16(m);
        }
        __syncthreads();
    }

    // ---- conv3: M=64, N=50 (2img x 25pos), K=128/tap; 8 warps m32n16, barrier-free ----
    {
        const int mg = wid & 1, ng = wid >> 1;           // ng 0..3
        const int njeff = (ng == 3) ? 1 : 2;
        float D0[2][4], D1[2][4];
        #pragma unroll
        for (int j = 0; j < 2; j++)
            #pragma unroll
            for (int k = 0; k < 4; k++) { D0[j][k] = 0.f; D1[j][k] = 0.f; }

        int rj[2], cj[2];
        uint32_t aj[2];
        #pragma unroll
        for (int j = 0; j < 2; j++) {
            int n = ng * 16 + j * 8 + rB;
            int img = n / 25, pos = n - img * 25;
            rj[j] = (n < 50) ? (pos / 5) : -100;
            cj[j] = pos - (pos / 5) * 5;
            aj[j] = sbase + (uint32_t)(S_POOL2 + img * 25 * 272 + hB);
        }
        const uint4* W = g_w3f + (mg * 2) * 256 + lane;   // + t*1024 + mt*256 + k*32

        for (int t = 0; t < 9; t++) {
            const int dy = t / 3 - 1, dx = t % 3 - 1;
            uint32_t bA[2];
            #pragma unroll
            for (int j = 0; j < 2; j++) {
                int rr = rj[j] + dy, cc = cj[j] + dx;
                bool ok = ((unsigned)rr < 5u) && ((unsigned)cc < 5u);
                bA[j] = ok ? aj[j] + (uint32_t)((rr * 5 + cc) * 272) : zAddr;
            }
            uint32_t bSel = hiSel ? ((njeff > 1) ? bA[1] : zAddr) : bA[0];
            const uint4* Wt = W + t * 1024;
            uint4 a0c = __ldg(Wt), a1c = __ldg(Wt + 256);
            #pragma unroll
            for (int k = 0; k < 8; k++) {
                uint4 a0n, a1n;
                if (k < 7) { a0n = __ldg(Wt + (k + 1) * 32); a1n = __ldg(Wt + 256 + (k + 1) * 32); }
                uint32_t b0, b1, b2, b3;
                ldmx4(b0, b1, b2, b3, bSel + 32 * k);
                mma16816(D0[0], a0c.x, a0c.y, a0c.z, a0c.w, b0, b1);
                mma16816(D1[0], a1c.x, a1c.y, a1c.z, a1c.w, b0, b1);
                if (njeff > 1) {
                    mma16816(D0[1], a0c.x, a0c.y, a0c.z, a0c.w, b2, b3);
                    mma16816(D1[1], a1c.x, a1c.y, a1c.z, a1c.w, b2, b3);
                }
                a0c = a0n; a1c = a1n;
            }
        }
        __syncthreads();
        #pragma unroll
        for (int mt = 0; mt < 2; mt++) {
            #pragma unroll
            for (int j = 0; j < 2; j++) {
                float* c = mt ? D1[j] : D0[j];
                int co = mg * 32 + mt * 16 + dlt;
                int n0 = ng * 16 + j * 8 + 2 * q;
                if (n0 < 50) {
                    float bAv = s_b3[co], bBv = s_b3[co + 8];
                    *(__nv_bfloat16*)(sm + S_ACT3 + n0 * 144 + co * 2) =
                        __float2bfloat16(fmaxf(c[0] + bAv, 0.f));
                    *(__nv_bfloat16*)(sm + S_ACT3 + (n0 + 1) * 144 + co * 2) =
                        __float2bfloat16(fmaxf(c[1] + bAv, 0.f));
                    *(__nv_bfloat16*)(sm + S_ACT3 + n0 * 144 + (co + 8) * 2) =
                        __float2bfloat16(fmaxf(c[2] + bBv, 0.f));
                    *(__nv_bfloat16*)(sm + S_ACT3 + (n0 + 1) * 144 + (co + 8) * 2) =
                        __float2bfloat16(fmaxf(c[3] + bBv, 0.f));
                }
            }
        }
        __syncthreads();
    }

    // ---- conv4: M=64, N=50, K=64/tap; 8 warps m32n16, barrier-free ----
    {
        const int mg = wid & 1, ng = wid >> 1;
        const int njeff = (ng == 3) ? 1 : 2;
        float D0[2][4], D1[2][4];
        #pragma unroll
        for (int j = 0; j < 2; j++)
            #pragma unroll
            for (int k = 0; k < 4; k++) { D0[j][k] = 0.f; D1[j][k] = 0.f; }

        int rj[2], cj[2];
        uint32_t aj[2];
        #pragma unroll
        for (int j = 0; j < 2; j++) {
            int n = ng * 16 + j * 8 + rB;
            int img = n / 25, pos = n - img * 25;
            rj[j] = (n < 50) ? (pos / 5) : -100;
            cj[j] = pos - (pos / 5) * 5;
            aj[j] = sbase + (uint32_t)(S_ACT3 + img * 25 * 144 + hB);
        }
        const uint4* W = g_w4f + (mg * 2) * 128 + lane;   // + t*512 + mt*128 + k*32

        for (int t = 0; t < 9; t++) {
            const int dy = t / 3 - 1, dx = t % 3 - 1;
            uint32_t bA[2];
            #pragma unroll
            for (int j = 0; j < 2; j++) {
                int rr = rj[j] + dy, cc = cj[j] + dx;
                bool ok = ((unsigned)rr < 5u) && ((unsigned)cc < 5u);
                bA[j] = ok ? aj[j] + (uint32_t)((rr * 5 + cc) * 144) : zAddr;
            }
            uint32_t bSel = hiSel ? ((njeff > 1) ? bA[1] : zAddr) : bA[0];
            const uint4* Wt = W + t * 512;
            uint4 a0c = __ldg(Wt), a1c = __ldg(Wt + 128);
            #pragma unroll
            for (int k = 0; k < 4; k++) {
                uint4 a0n, a1n;
                if (k < 3) { a0n = __ldg(Wt + (k + 1) * 32); a1n = __ldg(Wt + 128 + (k + 1) * 32); }
                uint32_t b0, b1, b2, b3;
                ldmx4(b0, b1, b2, b3, bSel + 32 * k);
                mma16816(D0[0], a0c.x, a0c.y, a0c.z, a0c.w, b0, b1);
                mma16816(D1[0], a1c.x, a1c.y, a1c.z, a1c.w, b0, b1);
                if (njeff > 1) {
                    mma16816(D0[1], a0c.x, a0c.y, a0c.z, a0c.w, b2, b3);
                    mma16816(D1[1], a1c.x, a1c.y, a1c.z, a1c.w, b2, b3);
                }
                a0c = a0n; a1c = a1n;
            }
        }
        __syncthreads();
        #pragma unroll
        for (int mt = 0; mt < 2; mt++) {
            #pragma unroll
            for (int j = 0; j < 2; j++) {
                float* c = mt ? D1[j] : D0[j];
                int co = mg * 32 + mt * 16 + dlt;
                int n0 = ng * 16 + j * 8 + 2 * q;
                if (n0 < 50) {
                    float bAv = s_b4[co], bBv = s_b4[co + 8];
                    __nv_bfloat162 v01 = __floats2bfloat162_rn(fmaxf(c[0] + bAv, 0.f),
                                                               fmaxf(c[1] + bAv, 0.f));
                    __nv_bfloat162 v23 = __floats2bfloat162_rn(fmaxf(c[2] + bBv, 0.f),
                                                               fmaxf(c[3] + bBv, 0.f));
                    *(uint32_t*)(sm + S_ACT4 + co * 208 + n0 * 2) = *(uint32_t*)&v01;
                    *(uint32_t*)(sm + S_ACT4 + (co + 8) * 208 + n0 * 2) = *(uint32_t*)&v23;
                }
            }
        }
        __syncthreads();
    }

    // ---- head: pool 2x2 -> mean -> dense -> sigmoid ----
    if (tid < 128) {
        int img = tid >> 6, c = tid & 63;
        const char* b = sm + S_ACT4 + c * 208 + img * 50;
        #define GA(p) __bfloat162float(*(const __nv_bfloat16*)(b + (p) * 2))
        float m00 = fmaxf(fmaxf(GA(0), GA(1)), fmaxf(GA(5), GA(6)));
        float m01 = fmaxf(fmaxf(GA(2), GA(3)), fmaxf(GA(7), GA(8)));
        float m10 = fmaxf(fmaxf(GA(10), GA(11)), fmaxf(GA(15), GA(16)));
        float m11 = fmaxf(fmaxf(GA(12), GA(13)), fmaxf(GA(17), GA(18)));
        #undef GA
        s_feat[img * 64 + c] = 0.25f * (m00 + m01 + m10 + m11);
    }
    __syncthreads();
    if (tid < 64) {
        int img = tid >> 5, jn = tid & 31;
        float acc = s_bd1[jn];
        #pragma unroll 8
        for (int c = 0; c < 64; c++) acc += s_feat[img * 64 + c] * __ldg(wd1 + c * 32 + jn);
        s_h[img * 32 + jn] = fmaxf(acc, 0.f);
    }
    __syncthreads();
    if (tid < 8) {
        int img = tid >> 2, k = tid & 3;
        float acc = s_bd2[k];
        #pragma unroll 8
        for (int j = 0; j < 32; j++) acc += s_h[img * 32 + j] * s_wd2[j * 4 + k];
        s_sv[img * 4 + k] = 1.f / (1.f + expf(-acc));
    }
    __syncthreads();
    if (tid < 2) {
        int gimg = blockIdx.x * 2 + tid;
        if (gimg < Btot) {
            const float* sv = s_sv + tid * 4;
            const float p1x = sv[0], p1y = sv[1], p2x = sv[2], p2y = sv[3];
            float px[5], py[5], pos[5];
            #pragma unroll
            for (int i = 0; i < 5; i++) {
                float t = 0.25f * (float)i;
                float x = rintf(((1.f - t) * p1x + t * p2x) * 10.f);
                float y = rintf(((1.f - t) * p1y + t * p2y) * 10.f);
                px[i] = x; py[i] = y;
                pos[i] = x * 10.f + y;
            }
            int ord[5] = {0, 1, 2, 3, 4};
            for (int i = 1; i < 5; i++) {
                int key = ord[i]; float kp = pos[key]; int j = i - 1;
                while (j >= 0 && pos[ord[j]] > kp) { ord[j + 1] = ord[j]; j--; }
                ord[j + 1] = key;
            }
            float ox[5], oy[5];
            #pragma unroll
            for (int i = 0; i < 5; i++) { ox[i] = px[ord[i]]; oy[i] = py[ord[i]]; }
            float o[10];
            #pragma unroll
            for (int i = 0; i < 10; i++) o[i] = -1.f;
            o[0] = ox[0]; o[1] = oy[0];
            int dst = 1;
            for (int i = 1; i < 5; i++) {
                float d = fabsf(ox[i] - ox[i - 1]) + fabsf(oy[i] - oy[i - 1]);
                if (d != 0.f) { o[2 * dst] = ox[i]; o[2 * dst + 1] = oy[i]; dst++; }
            }
            float* op = out + (long long)gimg * 10;
            #pragma unroll
            for (int i = 0; i < 10; i++) op[i] = o[i];
        }
    }
}

extern "C" void kernel_launch(void* const* d_in, const int* in_sizes, int n_in,
                              void* d_out, int out_size) {
    const float* data = (const float*)d_in[0];
    const float* w1   = (const float*)d_in[1];
    const float* b1   = (const float*)d_in[2];
    const float* w2   = (const float*)d_in[3];
    const float* b2   = (const float*)d_in[4];
    const float* w3   = (const float*)d_in[5];
    const float* b3   = (const float*)d_in[6];
    const float* w4   = (const float*)d_in[7];
    const float* b4   = (const float*)d_in[8];
    const float* wd1  = (const float*)d_in[9];
    const float* bd1  = (const float*)d_in[10];
    const float* wd2  = (const float*)d_in[11];
    const float* bd2  = (const float*)d_in[12];
    float* out = (float*)d_out;
    const int B = in_sizes[0] / 100;

    cudaFuncSetAttribute(img2svg_mma, cudaFuncAttributeMaxDynamicSharedMemorySize, SMEM_TOTAL);

    convert_weights<<<96, 256>>>(w2, w3, w4);
    img2svg_mma<<<(B + 1) / 2, NT, SMEM_TOTAL>>>(data, w1, b1, b2, b3, b4,
                                                 wd1, bd1, wd2, bd2, out, B);
}

// round 14
// speedup vs baseline: 1.3169x; 1.1578x over previous
#include <cuda_runtime.h>
#include <cuda_bf16.h>
#include <cstdint>

#define NT 256

// Fragment-major bf16 weights: each uint4 = one lane's mma-A fragment (a0,a1,a2,a3)
// conv2: [9 tap][8 mblk][8 kblk][32 lane]  = 18432 uint4
// conv3: [9 tap][4 mblk][8 kblk][32 lane]  = 9216 uint4
// conv4: [9 tap][4 mblk][4 kblk][32 lane]  = 4608 uint4
__device__ uint4 g_w2f[18432];
__device__ uint4 g_w3f[9216];
__device__ uint4 g_w4f[4608];

__global__ void convert_weights(const float* __restrict__ w2,
                                const float* __restrict__ w3,
                                const float* __restrict__ w4) {
    int gid = blockIdx.x * blockDim.x + threadIdx.x;
    int stride = gridDim.x * blockDim.x;
    for (int u = gid; u < 18432; u += stride) {
        int lane = u & 31, k = (u >> 5) & 7, mb = (u >> 8) & 7, tap = u >> 11;
        int r = lane >> 2, c0 = (lane & 3) * 2;
        int co = mb * 16 + r, ci = k * 16 + c0;
        const float* Wt = w2 + tap * 16384;
        uint4 v;
        __nv_bfloat162 p;
        p = __floats2bfloat162_rn(Wt[ci * 128 + co],       Wt[(ci + 1) * 128 + co]);       v.x = *(uint32_t*)&p;
        p = __floats2bfloat162_rn(Wt[ci * 128 + co + 8],   Wt[(ci + 1) * 128 + co + 8]);   v.y = *(uint32_t*)&p;
        p = __floats2bfloat162_rn(Wt[(ci + 8) * 128 + co], Wt[(ci + 9) * 128 + co]);       v.z = *(uint32_t*)&p;
        p = __floats2bfloat162_rn(Wt[(ci + 8) * 128 + co + 8], Wt[(ci + 9) * 128 + co + 8]); v.w = *(uint32_t*)&p;
        g_w2f[u] = v;
    }
    for (int u = gid; u < 9216; u += stride) {
        int lane = u & 31, k = (u >> 5) & 7, mb = (u >> 8) & 3, tap = u >> 10;
        int r = lane >> 2, c0 = (lane & 3) * 2;
        int co = mb * 16 + r, ci = k * 16 + c0;
        const float* Wt = w3 + tap * 8192;
        uint4 v;
        __nv_bfloat162 p;
        p = __floats2bfloat162_rn(Wt[ci * 64 + co],       Wt[(ci + 1) * 64 + co]);       v.x = *(uint32_t*)&p;
        p = __floats2bfloat162_rn(Wt[ci * 64 + co + 8],   Wt[(ci + 1) * 64 + co + 8]);   v.y = *(uint32_t*)&p;
        p = __floats2bfloat162_rn(Wt[(ci + 8) * 64 + co], Wt[(ci + 9) * 64 + co]);       v.z = *(uint32_t*)&p;
        p = __floats2bfloat162_rn(Wt[(ci + 8) * 64 + co + 8], Wt[(ci + 9) * 64 + co + 8]); v.w = *(uint32_t*)&p;
        g_w3f[u] = v;
    }
    for (int u = gid; u < 4608; u += stride) {
        int lane = u & 31, k = (u >> 5) & 3, mb = (u >> 7) & 3, tap = u >> 9;
        int r = lane >> 2, c0 = (lane & 3) * 2;
        int co = mb * 16 + r, ci = k * 16 + c0;
        const float* Wt = w4 + tap * 4096;
        uint4 v;
        __nv_bfloat162 p;
        p = __floats2bfloat162_rn(Wt[ci * 64 + co],       Wt[(ci + 1) * 64 + co]);       v.x = *(uint32_t*)&p;
        p = __floats2bfloat162_rn(Wt[ci * 64 + co + 8],   Wt[(ci + 1) * 64 + co + 8]);   v.y = *(uint32_t*)&p;
        p = __floats2bfloat162_rn(Wt[(ci + 8) * 64 + co], Wt[(ci + 9) * 64 + co]);       v.z = *(uint32_t*)&p;
        p = __floats2bfloat162_rn(Wt[(ci + 8) * 64 + co + 8], Wt[(ci + 9) * 64 + co + 8]); v.w = *(uint32_t*)&p;
        g_w4f[u] = v;
    }
}

// ---------------- SMEM layout (byte offsets), 2 images per CTA ----------------
#define S_ACT1   0          // 2 x [100 pos][136 ci] bf16 (stride 272B) = 54400
#define S_POOL2  54400      // [50][136] bf16 stride 272 = 13600
#define S_ACT3   68000      // [50][72] bf16 stride 144 = 7200
#define S_ZERO   75200      // 272 zero row
#define S_B2     75472
#define S_B3     75984
#define S_B4     76240
#define S_BD1    76496
#define S_BD2    76624
#define S_WD2    76640
#define S_FEAT   77152
#define S_H      77664
#define S_SV     77920
#define S_IMG    77952      // 2 x 144 padded f32 images = 1152
#define SMEM_TOTAL 79104
#define S_ACT4   0          // act4 scratch [64co][104n] stride 208 (act1 dead)

__device__ __forceinline__ uint32_t smem_u32(const void* p) {
    uint32_t a;
    asm("{ .reg .u64 t; cvta.to.shared.u64 t, %1; cvt.u32.u64 %0, t; }" : "=r"(a) : "l"(p));
    return a;
}

__device__ __forceinline__ void mma16816(float* c, uint32_t a0, uint32_t a1, uint32_t a2,
                                         uint32_t a3, uint32_t b0, uint32_t b1) {
    asm volatile(
        "mma.sync.aligned.m16n8k16.row.col.f32.bf16.bf16.f32 "
        "{%0,%1,%2,%3},{%4,%5,%6,%7},{%8,%9},{%0,%1,%2,%3};\n"
        : "+f"(c[0]), "+f"(c[1]), "+f"(c[2]), "+f"(c[3])
        : "r"(a0), "r"(a1), "r"(a2), "r"(a3), "r"(b0), "r"(b1));
}

__device__ __forceinline__ void ldmx4(uint32_t& b0, uint32_t& b1, uint32_t& b2, uint32_t& b3,
                                      uint32_t addr) {
    asm volatile("ldmatrix.sync.aligned.m8n8.x4.shared.b16 {%0,%1,%2,%3},[%4];"
                 : "=r"(b0), "=r"(b1), "=r"(b2), "=r"(b3) : "r"(addr));
}

__global__ __launch_bounds__(NT, 2)
void img2svg_mma(const float* __restrict__ data,
                 const float* __restrict__ w1, const float* __restrict__ b1,
                 const float* __restrict__ b2v, const float* __restrict__ b3v,
                 const float* __restrict__ b4v,
                 const float* __restrict__ wd1, const float* __restrict__ bd1,
                 const float* __restrict__ wd2, const float* __restrict__ bd2,
                 float* __restrict__ out, int Btot) {
    extern __shared__ char sm[];
    const int tid = threadIdx.x;
    const int wid = tid >> 5, lane = tid & 31;
    const int dlt = lane >> 2, q = lane & 3;
    const uint32_t sbase = smem_u32(sm);
    const int rB = lane & 7;                             // B row (n) within frag
    const int hB = ((lane >> 3) & 1) * 16;               // k-half byte offset
    const int hiSel = lane >> 4;                          // 0: frag 2u, 1: frag 2u+1
    const uint32_t zAddr = sbase + (uint32_t)(S_ZERO + hB);

    float* s_b2  = (float*)(sm + S_B2);
    float* s_b3  = (float*)(sm + S_B3);
    float* s_b4  = (float*)(sm + S_B4);
    float* s_bd1 = (float*)(sm + S_BD1);
    float* s_bd2 = (float*)(sm + S_BD2);
    float* s_wd2 = (float*)(sm + S_WD2);
    float* s_feat = (float*)(sm + S_FEAT);
    float* s_h   = (float*)(sm + S_H);
    float* s_sv  = (float*)(sm + S_SV);
    float* s_img = (float*)(sm + S_IMG);   // 2 x [12x12] padded

    // ---- init loads ----
    if (tid < 128) s_b2[tid] = b2v[tid];
    if (tid < 64)  s_b3[tid] = b3v[tid];
    if (tid < 64)  s_b4[tid] = b4v[tid];
    if (tid < 32)  s_bd1[tid] = bd1[tid];
    if (tid < 4)   s_bd2[tid] = bd2[tid];
    if (tid < 128) s_wd2[tid] = wd2[tid];
    if (tid < 68)  *(uint32_t*)(sm + S_ZERO + tid * 4) = 0u;
    {
        // padded image fill: each element decides border vs interior (no race, one pass)
        for (int e = tid; e < 288; e += NT) {
            int img = e >= 144, pp = e - img * 144;
            int r = pp / 12, c = pp - r * 12;
            float v = 0.f;
            if (r >= 1 && r <= 10 && c >= 1 && c <= 10) {
                long long gi = (long long)blockIdx.x * 200 + img * 100 + (r - 1) * 10 + (c - 1);
                v = (gi < (long long)Btot * 100) ? data[gi] : 0.f;
            }
            s_img[e] = v;
        }
    }
    __syncthreads();

    // ---- conv1: padded, branch-free, div-free. 1 -> 128, relu -> act1 bf16 ----
    {
        const int img = tid >> 7, co = tid & 127;
        const float* ip = s_img + img * 144;
        float wv[9];
        #pragma unroll
        for (int t = 0; t < 9; t++) wv[t] = w1[t * 128 + co];
        const float bias = b1[co];
        char* dst0 = sm + S_ACT1 + img * 27200 + co * 2;
        for (int r = 0; r < 10; r++) {
            const float* p0 = ip + r * 12;
            char* drow = dst0 + (r * 10) * 272;
            #pragma unroll
            for (int c = 0; c < 10; c++) {
                float acc = bias;
                acc += wv[0] * p0[c];
                acc += wv[1] * p0[c + 1];
                acc += wv[2] * p0[c + 2];
                acc += wv[3] * p0[c + 12];
                acc += wv[4] * p0[c + 13];
                acc += wv[5] * p0[c + 14];
                acc += wv[6] * p0[c + 24];
                acc += wv[7] * p0[c + 25];
                acc += wv[8] * p0[c + 26];
                *(__nv_bfloat16*)(drow + c * 272) = __float2bfloat16(fmaxf(acc, 0.f));
            }
        }
    }
    __syncthreads();

    // ---- conv2: per pass 1 image x 8 warps, warp m32 x n56, K=128/tap, barrier-free ----
    for (int p = 0; p < 2; p++) {
        const int mg = wid >> 1, ng = wid & 1;
        const int njeff = ng ? 6 : 7;
        const int npair = ng ? 3 : 4;
        float C0[7][4], C1[7][4];
        #pragma unroll
        for (int j = 0; j < 7; j++)
            #pragma unroll
            for (int k = 0; k < 4; k++) { C0[j][k] = 0.f; C1[j][k] = 0.f; }

        int rj[7], cj[7];
        #pragma unroll
        for (int j = 0; j < 7; j++) {
            int n = ng * 56 + j * 8 + rB;
            rj[j] = (n < 100) ? (n / 10) : -100;
            cj[j] = n - (n / 10) * 10;
        }
        const uint32_t bBase = sbase + (uint32_t)(S_ACT1 + p * 27200 + hB);
        const uint4* W = g_w2f + (mg * 2) * 256 + lane;    // + t*2048 + mt*256 + k*32

        for (int t = 0; t < 9; t++) {
            const int dy = t / 3 - 1, dx = t % 3 - 1;
            uint32_t bA[7];
            #pragma unroll
            for (int j = 0; j < 7; j++) {
                int rr = rj[j] + dy, cc = cj[j] + dx;
                bool ok = ((unsigned)rr < 10u) && ((unsigned)cc < 10u);
                bA[j] = ok ? bBase + (uint32_t)((rr * 10 + cc) * 272) : zAddr;
            }
            // per-lane dual-frag select: lanes<16 -> frag 2u, lanes>=16 -> frag 2u+1
            uint32_t bSel[4];
            bSel[0] = hiSel ? bA[1] : bA[0];
            bSel[1] = hiSel ? bA[3] : bA[2];
            bSel[2] = hiSel ? bA[5] : bA[4];
            bSel[3] = hiSel ? zAddr : bA[6];
            const uint4* Wt = W + t * 2048;
            uint4 a0c = __ldg(Wt), a1c = __ldg(Wt + 256);
            #pragma unroll
            for (int k = 0; k < 8; k++) {
                uint4 a0n, a1n;
                if (k < 7) { a0n = __ldg(Wt + (k + 1) * 32); a1n = __ldg(Wt + 256 + (k + 1) * 32); }
                #pragma unroll
                for (int u = 0; u < 4; u++) {
                    if (u < npair) {
                        uint32_t b0, b1, b2, b3;
                        ldmx4(b0, b1, b2, b3, bSel[u] + 32 * k);
                        mma16816(C0[2 * u], a0c.x, a0c.y, a0c.z, a0c.w, b0, b1);
                        mma16816(C1[2 * u], a1c.x, a1c.y, a1c.z, a1c.w, b0, b1);
                        if (2 * u + 1 < njeff) {
                            mma16816(C0[2 * u + 1], a0c.x, a0c.y, a0c.z, a0c.w, b2, b3);
                            mma16816(C1[2 * u + 1], a1c.x, a1c.y, a1c.z, a1c.w, b2, b3);
                        }
                    }
                }
                a0c = a0n; a1c = a1n;
            }
        }
        __syncthreads();   // all warps done reading act1[p]

        // epilogue: bias+relu -> scratch [co][104 n] (overlays act1 slot p)
        const uint32_t scr = S_ACT1 + (uint32_t)p * 27200;
        #pragma unroll
        for (int mt = 0; mt < 2; mt++) {
            #pragma unroll
            for (int j = 0; j < 7; j++) {
                float* c = mt ? C1[j] : C0[j];
                int co = mg * 32 + mt * 16 + dlt;
                int n0 = ng * 56 + j * 8 + 2 * q;
                if (n0 < 100) {
                    float bAv = s_b2[co], bBv = s_b2[co + 8];
                    __nv_bfloat162 v01 = __floats2bfloat162_rn(fmaxf(c[0] + bAv, 0.f),
                                                               fmaxf(c[1] + bAv, 0.f));
                    __nv_bfloat162 v23 = __floats2bfloat162_rn(fmaxf(c[2] + bBv, 0.f),
                                                               fmaxf(c[3] + bBv, 0.f));
                    *(uint32_t*)(sm + scr + co * 208 + n0 * 2) = *(uint32_t*)&v01;
                    *(uint32_t*)(sm + scr + (co + 8) * 208 + n0 * 2) = *(uint32_t*)&v23;
                }
            }
        }
        __syncthreads();
        // 2x2 maxpool -> pooled2[p*25+pp][ci]
        for (int e = tid; e < 3200; e += NT) {
            int co = e & 127, pp = e >> 7;
            int pr = pp / 5, pc = pp - pr * 5;
            int ntop = pr * 20 + pc * 2;
            uint32_t topw = *(uint32_t*)(sm + scr + co * 208 + ntop * 2);
            uint32_t botw = *(uint32_t*)(sm + scr + co * 208 + (ntop + 10) * 2);
            float2 tf = __bfloat1622float2(*(__nv_bfloat162*)&topw);
            float2 bf = __bfloat1622float2(*(__nv_bfloat162*)&botw);
            float m = fmaxf(fmaxf(tf.x, tf.y), fmaxf(bf.x, bf.y));
            *(__nv_bfloat16*)(sm + S_POOL2 + (p * 25 + pp) * 272 + co * 2) =
                __float2bfloat16(m);
        }
        __syncthreads();
    }

    // ---- conv3: M=64, N=50 (2img x 25pos), K=128/tap; 8 warps m32n16, barrier-free ----
    {
        const int mg = wid & 1, ng = wid >> 1;           // ng 0..3
        const int njeff = (ng == 3) ? 1 : 2;
        float D0[2][4], D1[2][4];
        #pragma unroll
        for (int j = 0; j < 2; j++)
            #pragma unroll
            for (int k = 0; k < 4; k++) { D0[j][k] = 0.f; D1[j][k] = 0.f; }

        int rj[2], cj[2];
        uint32_t aj[2];
        #pragma unroll
        for (int j = 0; j < 2; j++) {
            int n = ng * 16 + j * 8 + rB;
            int img = n / 25, pos = n - img * 25;
            rj[j] = (n < 50) ? (pos / 5) : -100;
            cj[j] = pos - (pos / 5) * 5;
            aj[j] = sbase + (uint32_t)(S_POOL2 + img * 25 * 272 + hB);
        }
        const uint4* W = g_w3f + (mg * 2) * 256 + lane;   // + t*1024 + mt*256 + k*32

        for (int t = 0; t < 9; t++) {
            const int dy = t / 3 - 1, dx = t % 3 - 1;
            uint32_t bA[2];
            #pragma unroll
            for (int j = 0; j < 2; j++) {
                int rr = rj[j] + dy, cc = cj[j] + dx;
                bool ok = ((unsigned)rr < 5u) && ((unsigned)cc < 5u);
                bA[j] = ok ? aj[j] + (uint32_t)((rr * 5 + cc) * 272) : zAddr;
            }
            uint32_t bSel = hiSel ? ((njeff > 1) ? bA[1] : zAddr) : bA[0];
            const uint4* Wt = W + t * 1024;
            uint4 a0c = __ldg(Wt), a1c = __ldg(Wt + 256);
            #pragma unroll
            for (int k = 0; k < 8; k++) {
                uint4 a0n, a1n;
                if (k < 7) { a0n = __ldg(Wt + (k + 1) * 32); a1n = __ldg(Wt + 256 + (k + 1) * 32); }
                uint32_t b0, b1, b2, b3;
                ldmx4(b0, b1, b2, b3, bSel + 32 * k);
                mma16816(D0[0], a0c.x, a0c.y, a0c.z, a0c.w, b0, b1);
                mma16816(D1[0], a1c.x, a1c.y, a1c.z, a1c.w, b0, b1);
                if (njeff > 1) {
                    mma16816(D0[1], a0c.x, a0c.y, a0c.z, a0c.w, b2, b3);
                    mma16816(D1[1], a1c.x, a1c.y, a1c.z, a1c.w, b2, b3);
                }
                a0c = a0n; a1c = a1n;
            }
        }
        __syncthreads();
        #pragma unroll
        for (int mt = 0; mt < 2; mt++) {
            #pragma unroll
            for (int j = 0; j < 2; j++) {
                float* c = mt ? D1[j] : D0[j];
                int co = mg * 32 + mt * 16 + dlt;
                int n0 = ng * 16 + j * 8 + 2 * q;
                if (n0 < 50) {
                    float bAv = s_b3[co], bBv = s_b3[co + 8];
                    *(__nv_bfloat16*)(sm + S_ACT3 + n0 * 144 + co * 2) =
                        __float2bfloat16(fmaxf(c[0] + bAv, 0.f));
                    *(__nv_bfloat16*)(sm + S_ACT3 + (n0 + 1) * 144 + co * 2) =
                        __float2bfloat16(fmaxf(c[1] + bAv, 0.f));
                    *(__nv_bfloat16*)(sm + S_ACT3 + n0 * 144 + (co + 8) * 2) =
                        __float2bfloat16(fmaxf(c[2] + bBv, 0.f));
                    *(__nv_bfloat16*)(sm + S_ACT3 + (n0 + 1) * 144 + (co + 8) * 2) =
                        __float2bfloat16(fmaxf(c[3] + bBv, 0.f));
                }
            }
        }
        __syncthreads();
    }

    // ---- conv4: M=64, N=50, K=64/tap; 8 warps m32n16, barrier-free ----
    {
        const int mg = wid & 1, ng = wid >> 1;
        const int njeff = (ng == 3) ? 1 : 2;
        float D0[2][4], D1[2][4];
        #pragma unroll
        for (int j = 0; j < 2; j++)
            #pragma unroll
            for (int k = 0; k < 4; k++) { D0[j][k] = 0.f; D1[j][k] = 0.f; }

        int rj[2], cj[2];
        uint32_t aj[2];
        #pragma unroll
        for (int j = 0; j < 2; j++) {
            int n = ng * 16 + j * 8 + rB;
            int img = n / 25, pos = n - img * 25;
            rj[j] = (n < 50) ? (pos / 5) : -100;
            cj[j] = pos - (pos / 5) * 5;
            aj[j] = sbase + (uint32_t)(S_ACT3 + img * 25 * 144 + hB);
        }
        const uint4* W = g_w4f + (mg * 2) * 128 + lane;   // + t*512 + mt*128 + k*32

        for (int t = 0; t < 9; t++) {
            const int dy = t / 3 - 1, dx = t % 3 - 1;
            uint32_t bA[2];
            #pragma unroll
            for (int j = 0; j < 2; j++) {
                int rr = rj[j] + dy, cc = cj[j] + dx;
                bool ok = ((unsigned)rr < 5u) && ((unsigned)cc < 5u);
                bA[j] = ok ? aj[j] + (uint32_t)((rr * 5 + cc) * 144) : zAddr;
            }
            uint32_t bSel = hiSel ? ((njeff > 1) ? bA[1] : zAddr) : bA[0];
            const uint4* Wt = W + t * 512;
            uint4 a0c = __ldg(Wt), a1c = __ldg(Wt + 128);
            #pragma unroll
            for (int k = 0; k < 4; k++) {
                uint4 a0n, a1n;
                if (k < 3) { a0n = __ldg(Wt + (k + 1) * 32); a1n = __ldg(Wt + 128 + (k + 1) * 32); }
                uint32_t b0, b1, b2, b3;
                ldmx4(b0, b1, b2, b3, bSel + 32 * k);
                mma16816(D0[0], a0c.x, a0c.y, a0c.z, a0c.w, b0, b1);
                mma16816(D1[0], a1c.x, a1c.y, a1c.z, a1c.w, b0, b1);
                if (njeff > 1) {
                    mma16816(D0[1], a0c.x, a0c.y, a0c.z, a0c.w, b2, b3);
                    mma16816(D1[1], a1c.x, a1c.y, a1c.z, a1c.w, b2, b3);
                }
                a0c = a0n; a1c = a1n;
            }
        }
        __syncthreads();
        #pragma unroll
        for (int mt = 0; mt < 2; mt++) {
            #pragma unroll
            for (int j = 0; j < 2; j++) {
                float* c = mt ? D1[j] : D0[j];
                int co = mg * 32 + mt * 16 + dlt;
                int n0 = ng * 16 + j * 8 + 2 * q;
                if (n0 < 50) {
                    float bAv = s_b4[co], bBv = s_b4[co + 8];
                    __nv_bfloat162 v01 = __floats2bfloat162_rn(fmaxf(c[0] + bAv, 0.f),
                                                               fmaxf(c[1] + bAv, 0.f));
                    __nv_bfloat162 v23 = __floats2bfloat162_rn(fmaxf(c[2] + bBv, 0.f),
                                                               fmaxf(c[3] + bBv, 0.f));
                    *(uint32_t*)(sm + S_ACT4 + co * 208 + n0 * 2) = *(uint32_t*)&v01;
                    *(uint32_t*)(sm + S_ACT4 + (co + 8) * 208 + n0 * 2) = *(uint32_t*)&v23;
                }
            }
        }
        __syncthreads();
    }

    // ---- head: pool 2x2 -> mean -> dense -> sigmoid ----
    if (tid < 128) {
        int img = tid >> 6, c = tid & 63;
        const char* b = sm + S_ACT4 + c * 208 + img * 50;
        #define GA(p) __bfloat162float(*(const __nv_bfloat16*)(b + (p) * 2))
        float m00 = fmaxf(fmaxf(GA(0), GA(1)), fmaxf(GA(5), GA(6)));
        float m01 = fmaxf(fmaxf(GA(2), GA(3)), fmaxf(GA(7), GA(8)));
        float m10 = fmaxf(fmaxf(GA(10), GA(11)), fmaxf(GA(15), GA(16)));
        float m11 = fmaxf(fmaxf(GA(12), GA(13)), fmaxf(GA(17), GA(18)));
        #undef GA
        s_feat[img * 64 + c] = 0.25f * (m00 + m01 + m10 + m11);
    }
    __syncthreads();
    if (tid < 64) {
        int img = tid >> 5, jn = tid & 31;
        float acc = s_bd1[jn];
        #pragma unroll 8
        for (int c = 0; c < 64; c++) acc += s_feat[img * 64 + c] * __ldg(wd1 + c * 32 + jn);
        s_h[img * 32 + jn] = fmaxf(acc, 0.f);
    }
    __syncthreads();
    if (tid < 8) {
        int img = tid >> 2, k = tid & 3;
        float acc = s_bd2[k];
        #pragma unroll 8
        for (int j = 0; j < 32; j++) acc += s_h[img * 32 + j] * s_wd2[j * 4 + k];
        s_sv[img * 4 + k] = 1.f / (1.f + expf(-acc));
    }
    __syncthreads();
    if (tid < 2) {
        int gimg = blockIdx.x * 2 + tid;
        if (gimg < Btot) {
            const float* sv = s_sv + tid * 4;
            const float p1x = sv[0], p1y = sv[1], p2x = sv[2], p2y = sv[3];
            float px[5], py[5], pos[5];
            #pragma unroll
            for (int i = 0; i < 5; i++) {
                float t = 0.25f * (float)i;
                float x = rintf(((1.f - t) * p1x + t * p2x) * 10.f);
                float y = rintf(((1.f - t) * p1y + t * p2y) * 10.f);
                px[i] = x; py[i] = y;
                pos[i] = x * 10.f + y;
            }
            int ord[5] = {0, 1, 2, 3, 4};
            for (int i = 1; i < 5; i++) {
                int key = ord[i]; float kp = pos[key]; int j = i - 1;
                while (j >= 0 && pos[ord[j]] > kp) { ord[j + 1] = ord[j]; j--; }
                ord[j + 1] = key;
            }
            float ox[5], oy[5];
            #pragma unroll
            for (int i = 0; i < 5; i++) { ox[i] = px[ord[i]]; oy[i] = py[ord[i]]; }
            float o[10];
            #pragma unroll
            for (int i = 0; i < 10; i++) o[i] = -1.f;
            o[0] = ox[0]; o[1] = oy[0];
            int dst = 1;
            for (int i = 1; i < 5; i++) {
                float d = fabsf(ox[i] - ox[i - 1]) + fabsf(oy[i] - oy[i - 1]);
                if (d != 0.f) { o[2 * dst] = ox[i]; o[2 * dst + 1] = oy[i]; dst++; }
            }
            float* op = out + (long long)gimg * 10;
            #pragma unroll
            for (int i = 0; i < 10; i++) op[i] = o[i];
        }
    }
}

extern "C" void kernel_launch(void* const* d_in, const int* in_sizes, int n_in,
                              void* d_out, int out_size) {
    const float* data = (const float*)d_in[0];
    const float* w1   = (const float*)d_in[1];
    const float* b1   = (const float*)d_in[2];
    const float* w2   = (const float*)d_in[3];
    const float* b2   = (const float*)d_in[4];
    const float* w3   = (const float*)d_in[5];
    const float* b3   = (const float*)d_in[6];
    const float* w4   = (const float*)d_in[7];
    const float* b4   = (const float*)d_in[8];
    const float* wd1  = (const float*)d_in[9];
    const float* bd1  = (const float*)d_in[10];
    const float* wd2  = (const float*)d_in[11];
    const float* bd2  = (const float*)d_in[12];
    float* out = (float*)d_out;
    const int B = in_sizes[0] / 100;

    cudaFuncSetAttribute(img2svg_mma, cudaFuncAttributeMaxDynamicSharedMemorySize, SMEM_TOTAL);

    convert_weights<<<96, 256>>>(w2, w3, w4);
    img2svg_mma<<<(B + 1) / 2, NT, SMEM_TOTAL>>>(data, w1, b1, b2, b3, b4,
                                                 wd1, bd1, wd2, bd2, out, B);
}